// round 17
// baseline (speedup 1.0000x reference)
#include <cuda_runtime.h>
#include <cstdint>

#define NATOMS   4096
#define BLOCK_SZ 512
#define BOXF     44.0f
#define INV_BOX  (1.0f / 44.0f)
#define CUT2     (17.5f * 17.5f)

#define T        256                        // tile size (atoms)
#define NTILE    (NATOMS / T)               // 16
#define NPAIR    (NTILE * (NTILE + 1) / 2)  // 136 CTAs -> single wave
#define TPB      512                        // 16 warps
#define NQUAD    (NATOMS * 3 / 4)           // 3072 float4s per slot

// half-row stages: 5 params x 128 floats = 640 floats = 2560 B
#define STGF      640                        // floats per stage
#define NBUF      5                          // buffers per warp (distance-4 pipeline)
#define WBUFF     (NBUF * STGF)              // 3200 floats per warp
#define SBUF_FLOATS (16 * WBUFF)             // 51200 floats = 200 KB (fcolp aliased here)
#define SMEM_FLOATS (SBUF_FLOATS + T * 3 + 16)
#define SMEM_BYTES  (SMEM_FLOATS * 4)        // 207,936 B

// deterministic scratch
__device__ float g_fpart[NTILE * NATOMS * 3];   // [slot][atom][xyz]
__device__ float g_ecta[NPAIR];

__inline__ __device__ float warp_sum(float v) {
    #pragma unroll
    for (int o = 16; o > 0; o >>= 1) v += __shfl_down_sync(0xffffffffu, v, o);
    return v;
}

__inline__ __device__ uint32_t su32(const void* p) {
    uint32_t a;
    asm("{ .reg .u64 t; cvta.to.shared.u64 t, %1; cvt.u32.u64 %0, t; }" : "=r"(a) : "l"(p));
    return a;
}

__device__ __forceinline__ void cp16(uint32_t s, const float* g) {
    asm volatile("cp.async.cg.shared.global [%0], [%1], 16;" :: "r"(s), "l"(g));
}

// stage one half-row (5 params x 512B); lane copies its own 16B of each param
__device__ __forceinline__ void stage_half(
    const float* __restrict__ A, const float* __restrict__ C,
    const float* __restrict__ D, const float* __restrict__ RHO,
    const float* __restrict__ SIG,
    size_t o /* global float idx incl lane*4 */, uint32_t d /* smem dst incl lane*16 */)
{
    cp16(d,        A   + o);
    cp16(d + 512,  C   + o);
    cp16(d + 1024, D   + o);
    cp16(d + 1536, RHO + o);
    cp16(d + 2048, SIG + o);
    asm volatile("cp.async.commit_group;" ::: "memory");
}

// one pair: accumulates energy, returns g*r components
__inline__ __device__ void pm(float dx, float dy, float dz,
                              float a, float c, float dd, float rh, float sg,
                              bool ok0,
                              float& en, float& gx, float& gy, float& gz)
{
    dx -= rintf(dx * INV_BOX) * BOXF;
    dy -= rintf(dy * INV_BOX) * BOXF;
    dz -= rintf(dz * INV_BOX) * BOXF;
    const float r2 = fmaf(dx, dx, fmaf(dy, dy, dz * dz));

    const bool  ok = ok0 && (r2 < CUT2);
    const float we = ok ? 1.0f : 0.0f;
    const float wf = (ok && r2 > 1.0f) ? 1.0f : 0.0f;

    const float r2c  = fmaxf(r2, 1.0f);
    const float dinv = rsqrtf(r2c);
    const float dij  = r2c * dinv;

    const float invrh = __fdividef(1.0f, rh);
    const float e     = __expf((sg - dij) * invrh);

    const float inv2 = dinv * dinv;
    const float inv6 = inv2 * inv2 * inv2;
    const float inv8 = inv6 * inv2;

    const float ae = a * e;
    const float pe = fmaf(dd, inv8, fmaf(-c, inv6, ae));
    en = fmaf(we, pe, en);

    float g = fmaf(6.0f * c, inv8,
                   fmaf(-8.0f * dd, inv8 * inv2,
                        -(ae * invrh) * dinv));
    g *= wf;
    gx = g * dx; gy = g * dy; gz = g * dz;
}

// 4 pairs of half H (H literal 0/1): cols jcl..jcl+3, fjx indices 4H..4H+3
#define PM4(a4, c4, d4, r4, s4, H)                                               \
    {                                                                             \
        float gx, gy, gz;                                                         \
        pm(xi - xj[4*(H)+0], yi - yj[4*(H)+0], zi - zj[4*(H)+0],                  \
           a4.x, c4.x, d4.x, r4.x, s4.x,                                          \
           (dloc != 0) && (!DIAG || irel < 0), en, gx, gy, gz);                   \
        prx += gx; pry += gy; prz += gz;                                          \
        fjx[4*(H)+0] -= gx; fjy[4*(H)+0] -= gy; fjz[4*(H)+0] -= gz;               \
        pm(xi - xj[4*(H)+1], yi - yj[4*(H)+1], zi - zj[4*(H)+1],                  \
           a4.y, c4.y, d4.y, r4.y, s4.y,                                          \
           (dloc != 1) && (!DIAG || irel < 1), en, gx, gy, gz);                   \
        prx += gx; pry += gy; prz += gz;                                          \
        fjx[4*(H)+1] -= gx; fjy[4*(H)+1] -= gy; fjz[4*(H)+1] -= gz;               \
        pm(xi - xj[4*(H)+2], yi - yj[4*(H)+2], zi - zj[4*(H)+2],                  \
           a4.z, c4.z, d4.z, r4.z, s4.z,                                          \
           (dloc != 2) && (!DIAG || irel < 2), en, gx, gy, gz);                   \
        prx += gx; pry += gy; prz += gz;                                          \
        fjx[4*(H)+2] -= gx; fjy[4*(H)+2] -= gy; fjz[4*(H)+2] -= gz;               \
        pm(xi - xj[4*(H)+3], yi - yj[4*(H)+3], zi - zj[4*(H)+3],                  \
           a4.w, c4.w, d4.w, r4.w, s4.w,                                          \
           (dloc != 3) && (!DIAG || irel < 3), en, gx, gy, gz);                   \
        prx += gx; pry += gy; prz += gz;                                          \
        fjx[4*(H)+3] -= gx; fjy[4*(H)+3] -= gy; fjz[4*(H)+3] -= gz;               \
    }

template<bool DIAG>
__device__ __forceinline__ void tile_body(
    int ti, int tj, int bidx,
    const float* __restrict__ coords,
    const float* __restrict__ A, const float* __restrict__ C,
    const float* __restrict__ D, const float* __restrict__ RHO,
    const float* __restrict__ SIG)
{
    extern __shared__ float smem_dyn[];
    float* sbuf  = smem_dyn;                        // stage region (fcolp aliased)
    float* fcolp = smem_dyn;                        // [16][768] — used AFTER staging done
    float* frow  = smem_dyn + SBUF_FLOATS;          // [256][3]
    float* esm   = frow + T * 3;                    // [16]

    const int t    = threadIdx.x;
    const int lane = t & 31;
    const int w    = t >> 5;                 // warp 0..15

    const float wbase = ((ti >> 1) == (tj >> 1)) ? 1.0f : 2.0f;

    // column coords for this lane's 8 cols: h=0 -> 4*lane.., h=1 -> 128+4*lane..
    float xj[8], yj[8], zj[8];
    {
        const float4* c0 = (const float4*)(coords + 3 * (size_t)(tj * T + 4 * lane));
        const float4 q0 = __ldg(c0 + 0), q1 = __ldg(c0 + 1), q2 = __ldg(c0 + 2);
        xj[0]=q0.x; yj[0]=q0.y; zj[0]=q0.z;  xj[1]=q0.w; yj[1]=q1.x; zj[1]=q1.y;
        xj[2]=q1.z; yj[2]=q1.w; zj[2]=q2.x;  xj[3]=q2.y; yj[3]=q2.z; zj[3]=q2.w;
        const float4* c1 = (const float4*)(coords + 3 * (size_t)(tj * T + 128 + 4 * lane));
        const float4 p0 = __ldg(c1 + 0), p1 = __ldg(c1 + 1), p2 = __ldg(c1 + 2);
        xj[4]=p0.x; yj[4]=p0.y; zj[4]=p0.z;  xj[5]=p0.w; yj[5]=p1.x; zj[5]=p1.y;
        xj[6]=p1.z; yj[6]=p1.w; zj[6]=p2.x;  xj[7]=p2.y; yj[7]=p2.z; zj[7]=p2.w;
    }
    const int locj0_0 = (tj * T + 4 * lane)       & (BLOCK_SZ - 1);
    const int locj0_1 = (tj * T + 128 + 4 * lane) & (BLOCK_SZ - 1);

    float fjx[8], fjy[8], fjz[8];
    #pragma unroll
    for (int c = 0; c < 8; ++c) { fjx[c] = 0.f; fjy[c] = 0.f; fjz[c] = 0.f; }
    float en = 0.f;

    float* wbuf = sbuf + w * WBUFF;
    const uint32_t sbw = su32(wbuf) + lane * 16;

    // warp w's rows: i = r*16 + w; stage s = 2r + h covers cols [h*128, h*128+128)
    const size_t row0 = (size_t)(ti * T + w) * NATOMS + tj * T;

    // prologue: stage stages 0..3 (rows 0-1, both halves)
    #pragma unroll
    for (int s = 0; s < 4; ++s) {
        const size_t o = row0 + (size_t)((s >> 1) * 16) * NATOMS + (s & 1) * 128 + lane * 4;
        stage_half(A, C, D, RHO, SIG, o, sbw + (uint32_t)(s * STGF * 4));
    }

    int bcur = 0;      // buffer of stage s
    int bnext = 4;     // buffer of stage s+4
    float rrx = 0.f, rry = 0.f, rrz = 0.f;
    float xi = 0.f, yi = 0.f, zi = 0.f;
    int igrow = 0;

    #pragma unroll 1
    for (int r = 0; r < 16; ++r) {
        #pragma unroll
        for (int h = 0; h < 2; ++h) {
            const int s = 2 * r + h;
            // prefetch stage s+4 / drain to make stage s ready
            if (s < 28) {
                const int t2 = s + 4;
                const size_t o = row0 + (size_t)((t2 >> 1) * 16) * NATOMS
                               + (t2 & 1) * 128 + lane * 4;
                stage_half(A, C, D, RHO, SIG, o, sbw + (uint32_t)(bnext * STGF * 4));
                asm volatile("cp.async.wait_group 4;" ::: "memory");
            } else if (s == 28) { asm volatile("cp.async.wait_group 3;" ::: "memory"); }
            else   if (s == 29) { asm volatile("cp.async.wait_group 2;" ::: "memory"); }
            else   if (s == 30) { asm volatile("cp.async.wait_group 1;" ::: "memory"); }
            else                { asm volatile("cp.async.wait_group 0;" ::: "memory"); }

            const float* lp = wbuf + bcur * STGF + 4 * lane;
            const float4 a4 = *(const float4*)(lp + 0 * 128);
            const float4 c4 = *(const float4*)(lp + 1 * 128);
            const float4 d4 = *(const float4*)(lp + 2 * 128);
            const float4 r4 = *(const float4*)(lp + 3 * 128);
            const float4 s4 = *(const float4*)(lp + 4 * 128);

            const int i  = r * 16 + w;
            if (h == 0) {
                igrow = ti * T + i;
                xi = __ldg(&coords[3 * igrow + 0]);
                yi = __ldg(&coords[3 * igrow + 1]);
                zi = __ldg(&coords[3 * igrow + 2]);
            }
            const int jcl  = h * 128 + 4 * lane;
            const int dloc = (igrow & (BLOCK_SZ - 1)) - (h ? locj0_1 : locj0_0);
            const int irel = i - jcl;

            float prx = 0.f, pry = 0.f, prz = 0.f;
            if (h == 0) { PM4(a4, c4, d4, r4, s4, 0) }
            else        { PM4(a4, c4, d4, r4, s4, 1) }

            if (h == 0) { rrx = prx; rry = pry; rrz = prz; }
            else {
                rrx += prx; rry += pry; rrz += prz;
                rrx = warp_sum(rrx); rry = warp_sum(rry); rrz = warp_sum(rrz);
                if (lane == 0) {
                    frow[i * 3 + 0] = rrx; frow[i * 3 + 1] = rry; frow[i * 3 + 2] = rrz;
                }
            }

            if (++bcur == NBUF)  bcur = 0;
            if (++bnext == NBUF) bnext = 0;
        }
    }

    // energy partial (before barrier; esm is a separate region)
    en = warp_sum(en);
    if (lane == 0) esm[w] = en;

    __syncthreads();   // ALL warps' staging complete -> safe to alias fcolp over sbuf

    // stash per-warp column partials: col = h*128 + 4*lane + q, c = 4h+q
    {
        float* cp = fcolp + w * (T * 3);
        #pragma unroll
        for (int c = 0; c < 8; ++c) {
            const int col = (c >> 2) * 128 + 4 * lane + (c & 3);
            cp[3 * col + 0] = fjx[c];
            cp[3 * col + 1] = fjy[c];
            cp[3 * col + 2] = fjz[c];
        }
    }
    __syncthreads();

    if (t < T) {
        float rx = frow[t * 3 + 0], ry = frow[t * 3 + 1], rz = frow[t * 3 + 2];
        if (DIAG) {
            #pragma unroll
            for (int ww = 0; ww < 16; ++ww) {
                rx += fcolp[ww * (T * 3) + t * 3 + 0];
                ry += fcolp[ww * (T * 3) + t * 3 + 1];
                rz += fcolp[ww * (T * 3) + t * 3 + 2];
            }
        }
        float* dst = g_fpart + ((size_t)tj * NATOMS + ti * T + t) * 3;
        dst[0] = wbase * rx; dst[1] = wbase * ry; dst[2] = wbase * rz;
    } else if (!DIAG) {
        const int c = t - T;
        float cx = 0.f, cy = 0.f, cz = 0.f;
        #pragma unroll
        for (int ww = 0; ww < 16; ++ww) {
            cx += fcolp[ww * (T * 3) + c * 3 + 0];
            cy += fcolp[ww * (T * 3) + c * 3 + 1];
            cz += fcolp[ww * (T * 3) + c * 3 + 2];
        }
        float* dst = g_fpart + ((size_t)ti * NATOMS + tj * T + c) * 3;
        dst[0] = wbase * cx; dst[1] = wbase * cy; dst[2] = wbase * cz;
    }

    if (t < 32) {
        float v = (t < TPB / 32) ? esm[t] : 0.f;
        v = warp_sum(v);
        if (t == 0) g_ecta[bidx] = wbase * v;
    }
}

__global__ __launch_bounds__(TPB)
void bmh_tile_kernel(const float* __restrict__ coords,
                     const float* __restrict__ A,
                     const float* __restrict__ C,
                     const float* __restrict__ D,
                     const float* __restrict__ RHO,
                     const float* __restrict__ SIG)
{
    int k = blockIdx.x, ti = 0, rem = NTILE;
    while (k >= rem) { k -= rem; ++ti; --rem; }
    const int tj = ti + k;

    if (ti == tj)
        tile_body<true >(ti, tj, blockIdx.x, coords, A, C, D, RHO, SIG);
    else
        tile_body<false>(ti, tj, blockIdx.x, coords, A, C, D, RHO, SIG);
}

// reduce: 24 CTAs x 128 threads + 1 energy CTA (proven minimal tail)
#define RTPB 128

__global__ __launch_bounds__(RTPB)
void bmh_reduce_kernel(float* __restrict__ out)
{
    const int tid = threadIdx.x;
    const int b   = blockIdx.x;

    if (b < 24) {
        const int q = b * RTPB + tid;         // 0..3071
        const float4* fp = (const float4*)g_fpart;
        float sx = 0.f, sy = 0.f, sz = 0.f, sw = 0.f;
        #pragma unroll
        for (int p = 0; p < NTILE; ++p) {
            const float4 v = fp[(size_t)p * NQUAD + q];
            sx += v.x; sy += v.y; sz += v.z; sw += v.w;
        }
        float* dst = out + 1 + q * 4;
        dst[0] = sx; dst[1] = sy; dst[2] = sz; dst[3] = sw;
    } else {
        double s = 0.0;
        for (int k2 = tid; k2 < NPAIR; k2 += RTPB) s += (double)g_ecta[k2];
        __shared__ double sd[RTPB];
        sd[tid] = s;
        __syncthreads();
        #pragma unroll
        for (int o = RTPB / 2; o > 0; o >>= 1) {
            if (tid < o) sd[tid] += sd[tid + o];
            __syncthreads();
        }
        if (tid == 0) out[0] = (float)sd[0];
    }
}

extern "C" void kernel_launch(void* const* d_in, const int* in_sizes, int n_in,
                              void* d_out, int out_size)
{
    const float* coords = (const float*)d_in[0];
    // d_in[1] = q (computed-but-unused upstream; faithfully ignored)
    const float* A   = (const float*)d_in[2];
    const float* C   = (const float*)d_in[3];
    const float* D   = (const float*)d_in[4];
    const float* RHO = (const float*)d_in[5];
    const float* SIG = (const float*)d_in[6];
    float* out = (float*)d_out;

    cudaFuncSetAttribute(bmh_tile_kernel,
                         cudaFuncAttributeMaxDynamicSharedMemorySize, SMEM_BYTES);
    bmh_tile_kernel<<<NPAIR, TPB, SMEM_BYTES>>>(coords, A, C, D, RHO, SIG);
    bmh_reduce_kernel<<<25, RTPB>>>(out);
}